// round 3
// baseline (speedup 1.0000x reference)
#include <cuda_runtime.h>

#define N_NODES 10000
#define N_EDGES 320000
#define HID 128
#define H3 384
#define NRBF 20
#define EPB 64      // edges per block (edge kernel)
#define KCH 32      // Wf2 k-rows per staged chunk

typedef unsigned long long ull;

// scratch: node MLP output x = silu(q@W1+b1)@W2+b2, [N, 384]
__device__ float g_x[N_NODES * H3];
__device__ int g_idx64;

__device__ __forceinline__ float silu_f(float v) {
    return v / (1.0f + __expf(-v));
}
__device__ __forceinline__ ull pack2(float lo, float hi) {
    ull r;
    asm("mov.b64 %0,{%1,%2};" : "=l"(r) : "f"(lo), "f"(hi));
    return r;
}
__device__ __forceinline__ void unpack2(ull v, float& lo, float& hi) {
    asm("mov.b64 {%0,%1},%2;" : "=f"(lo), "=f"(hi) : "l"(v));
}
// packed f32x2 FMA — ptxas never emits this from C++; 2x fma-pipe throughput
__device__ __forceinline__ ull fma2(ull a, ull b, ull c) {
    ull d;
    asm("fma.rn.f32x2 %0,%1,%2,%3;" : "=l"(d) : "l"(a), "l"(b), "l"(c));
    return d;
}
// vector atomic: 1 red op covers 4 floats
__device__ __forceinline__ void red_add_v4(float* p, float4 v) {
    asm volatile("red.global.add.v4.f32 [%0],{%1,%2,%3,%4};"
                 :: "l"(p), "f"(v.x), "f"(v.y), "f"(v.z), "f"(v.w) : "memory");
}
__device__ __forceinline__ void cp_async16(void* sdst, const void* gsrc) {
    unsigned s = (unsigned)__cvta_generic_to_shared(sdst);
    asm volatile("cp.async.cg.shared.global [%0],[%1],16;" :: "r"(s), "l"(gsrc));
}
__device__ __forceinline__ void cp_commit() {
    asm volatile("cp.async.commit_group;");
}
template <int N>
__device__ __forceinline__ void cp_wait() {
    asm volatile("cp.async.wait_group %0;" :: "n"(N));
}

// ---------------------------------------------------------------------------
// Kernel 1: out = concat(q, mu); detect int32 vs int64 edge_index layout.
// ---------------------------------------------------------------------------
__global__ void init_out(const float* __restrict__ q,
                         const float* __restrict__ mu,
                         float* __restrict__ out,
                         const int* __restrict__ ei32) {
    if (blockIdx.x == 0 && threadIdx.x == 0) {
        int flag = 1;
        #pragma unroll
        for (int i = 0; i < 16; i++)
            if (ei32[2 * i + 1] != 0) flag = 0;
        g_idx64 = flag;
    }
    int i = blockIdx.x * blockDim.x + threadIdx.x;
    const int nq4 = N_NODES * HID / 4;
    const int nm4 = N_NODES * H3 / 4;
    float4* o4 = (float4*)out;
    if (i < nq4)            o4[i] = ((const float4*)q)[i];
    else if (i < nq4 + nm4) o4[i] = ((const float4*)mu)[i - nq4];
}

// ---------------------------------------------------------------------------
// Kernel 2: node MLP with f32x2 packed math. 16 nodes/block (8 packed pairs),
// 384 threads = one output column per thread.
// ---------------------------------------------------------------------------
__global__ __launch_bounds__(384) void node_mlp(const float* __restrict__ q,
                                                const float* __restrict__ W1,
                                                const float* __restrict__ b1,
                                                const float* __restrict__ W2,
                                                const float* __restrict__ b2) {
    __shared__ float qs[16 * HID];  // 8 KB staging
    __shared__ ull qs2[HID * 8];    // 8 KB packed pairs [k][j]
    __shared__ ull t1p[H3 * 8];     // 24 KB packed hidden [k][j]
    const int n0 = blockIdx.x * 16;
    const int tid = threadIdx.x;

    for (int i = tid; i < 16 * HID; i += 384) qs[i] = q[n0 * HID + i];
    __syncthreads();
    for (int i = tid; i < HID * 8; i += 384) {
        int k = i >> 3, j = i & 7;
        qs2[k * 8 + j] = pack2(qs[(2 * j) * HID + k], qs[(2 * j + 1) * HID + k]);
    }
    __syncthreads();

    const int c = tid;  // 0..383
    // layer 1
    {
        ull a[8];
        float bb = __ldg(&b1[c]);
        ull bp = pack2(bb, bb);
        #pragma unroll
        for (int j = 0; j < 8; j++) a[j] = bp;
        #pragma unroll 4
        for (int k = 0; k < HID; k++) {
            float w = __ldg(&W1[k * H3 + c]);
            ull ww = pack2(w, w);
            const ulonglong2* qp = (const ulonglong2*)(qs2 + k * 8);
            ulonglong2 p0 = qp[0], p1 = qp[1], p2 = qp[2], p3 = qp[3];
            a[0] = fma2(p0.x, ww, a[0]); a[1] = fma2(p0.y, ww, a[1]);
            a[2] = fma2(p1.x, ww, a[2]); a[3] = fma2(p1.y, ww, a[3]);
            a[4] = fma2(p2.x, ww, a[4]); a[5] = fma2(p2.y, ww, a[5]);
            a[6] = fma2(p3.x, ww, a[6]); a[7] = fma2(p3.y, ww, a[7]);
        }
        #pragma unroll
        for (int j = 0; j < 8; j++) {
            float lo, hi;
            unpack2(a[j], lo, hi);
            t1p[c * 8 + j] = pack2(silu_f(lo), silu_f(hi));
        }
    }
    __syncthreads();
    // layer 2
    {
        ull a[8];
        float bb = __ldg(&b2[c]);
        ull bp = pack2(bb, bb);
        #pragma unroll
        for (int j = 0; j < 8; j++) a[j] = bp;
        #pragma unroll 4
        for (int k = 0; k < H3; k++) {
            float w = __ldg(&W2[k * H3 + c]);
            ull ww = pack2(w, w);
            const ulonglong2* tp = (const ulonglong2*)(t1p + k * 8);
            ulonglong2 p0 = tp[0], p1 = tp[1], p2 = tp[2], p3 = tp[3];
            a[0] = fma2(p0.x, ww, a[0]); a[1] = fma2(p0.y, ww, a[1]);
            a[2] = fma2(p1.x, ww, a[2]); a[3] = fma2(p1.y, ww, a[3]);
            a[4] = fma2(p2.x, ww, a[4]); a[5] = fma2(p2.y, ww, a[5]);
            a[6] = fma2(p3.x, ww, a[6]); a[7] = fma2(p3.y, ww, a[7]);
        }
        #pragma unroll
        for (int j = 0; j < 8; j++) {
            float lo, hi;
            unpack2(a[j], lo, hi);
            g_x[(n0 + 2 * j) * H3 + c] = lo;
            g_x[(n0 + 2 * j + 1) * H3 + c] = hi;
        }
    }
}

// ---------------------------------------------------------------------------
// Kernel 3: fused edge kernel, Wf2 staged in smem (double-buffered cp.async).
// 64 edges/block, 8 warps, 8 edges/warp. Lane owns 4 cols per part.
// ---------------------------------------------------------------------------
// dynamic smem layout (bytes):
//   h1s   [EPB][HID] ull (pre-packed h,h)      @ 0        (65536)
//   wbuf  [2][KCH][H3] float                   @ 65536    (98304)
//   Wf1s  [NRBF*HID] float                     @ 163840   (10240)
//   rbfs  [EPB*NRBF] float                     @ 174080   (5120)
//   bf1s  [HID] float                          @ 179200   (512)
//   bf2s  [H3] float                           @ 179712   (1536)
//   cuts  [EPB] float                          @ 181248   (256)
//   uvs   [EPB*3] float                        @ 181504   (768)
//   srcs  [EPB] int                            @ 182272   (256)
//   tgts  [EPB] int                            @ 182528   (256)
#define SMEM_EDGE 182784

__device__ __forceinline__ void gemm_chunk(const float* __restrict__ wch,
                                           const ull* __restrict__ h1,
                                           int kbase, int eb, int lane,
                                           ull (&acc)[8][6]) {
    #pragma unroll 4
    for (int kk = 0; kk < KCH; kk++) {
        const ulonglong2* row = (const ulonglong2*)(wch + kk * H3);
        ulonglong2 wq = row[lane];
        ulonglong2 wr = row[32 + lane];
        ulonglong2 wm = row[64 + lane];
        const ull* hp = h1 + eb * HID + kbase + kk;
        #pragma unroll
        for (int e = 0; e < 8; e++) {
            ull h2 = hp[e * HID];
            acc[e][0] = fma2(h2, wq.x, acc[e][0]);
            acc[e][1] = fma2(h2, wq.y, acc[e][1]);
            acc[e][2] = fma2(h2, wr.x, acc[e][2]);
            acc[e][3] = fma2(h2, wr.y, acc[e][3]);
            acc[e][4] = fma2(h2, wm.x, acc[e][4]);
            acc[e][5] = fma2(h2, wm.y, acc[e][5]);
        }
    }
}

__global__ __launch_bounds__(256) void edge_kernel(
        const int* __restrict__ ei32, const long long* __restrict__ ei64,
        const float* __restrict__ rbf, const float* __restrict__ uv,
        const float* __restrict__ cut,
        const float* __restrict__ Wf1, const float* __restrict__ bf1,
        const float* __restrict__ Wf2, const float* __restrict__ bf2,
        const float* __restrict__ mu, float* __restrict__ out) {
    extern __shared__ char smem[];
    ull*   h1s  = (ull*)smem;
    float* wbuf = (float*)(smem + 65536);
    float* Wf1s = (float*)(smem + 163840);
    float* rbfs = (float*)(smem + 174080);
    float* bf1s = (float*)(smem + 179200);
    float* bf2s = (float*)(smem + 179712);
    float* cuts = (float*)(smem + 181248);
    float* uvs  = (float*)(smem + 181504);
    int*   srcs = (int*)(smem + 182272);
    int*   tgts = (int*)(smem + 182528);

    const int tid = threadIdx.x;
    const int e0 = blockIdx.x * EPB;
    const int F4 = KCH * H3 / 4;  // float4 per chunk = 3072

    // stage Wf2 chunks 0 and 1 first so they overlap phase A
    const float4* wsrc = (const float4*)Wf2;
    {
        float4* d0 = (float4*)wbuf;
        for (int i = tid; i < F4; i += 256) cp_async16(d0 + i, wsrc + i);
        cp_commit();
        float4* d1 = (float4*)(wbuf + KCH * H3);
        for (int i = tid; i < F4; i += 256) cp_async16(d1 + i, wsrc + F4 + i);
        cp_commit();
    }

    for (int i = tid; i < NRBF * HID; i += 256) Wf1s[i] = Wf1[i];
    for (int i = tid; i < EPB * NRBF; i += 256) rbfs[i] = rbf[e0 * NRBF + i];
    for (int i = tid; i < H3; i += 256)         bf2s[i] = bf2[i];
    if (tid < HID) bf1s[tid] = bf1[tid];
    if (tid < EPB) {
        int e = e0 + tid;
        cuts[tid] = cut[e];
        if (g_idx64) { tgts[tid] = (int)ei64[e]; srcs[tid] = (int)ei64[N_EDGES + e]; }
        else         { tgts[tid] = ei32[e];      srcs[tid] = ei32[N_EDGES + e]; }
    }
    for (int i = tid; i < EPB * 3; i += 256) uvs[i] = uv[e0 * 3 + i];
    __syncthreads();

    // Phase A: h1 = silu(rbf@Wf1+bf1), stored packed (h,h)
    for (int i = tid; i < EPB * HID; i += 256) {
        int e = i >> 7, j = i & 127;
        float a = bf1s[j];
        #pragma unroll
        for (int k = 0; k < NRBF; k++) a += rbfs[e * NRBF + k] * Wf1s[k * HID + j];
        float s = silu_f(a);
        h1s[i] = pack2(s, s);
    }

    // Phase B: filter GEMM over 4 double-buffered chunks
    const int warp = tid >> 5, lane = tid & 31;
    const int eb = warp * 8;
    ull acc[8][6];
    #pragma unroll
    for (int a = 0; a < 8; a++)
        #pragma unroll
        for (int b = 0; b < 6; b++) acc[a][b] = 0ull;

    cp_wait<1>();
    __syncthreads();   // h1 ready + chunk0 ready
    gemm_chunk(wbuf, h1s, 0, eb, lane, acc);
    __syncthreads();
    {   // stage chunk2 into buf0
        float4* d = (float4*)wbuf;
        for (int i = tid; i < F4; i += 256) cp_async16(d + i, wsrc + 2 * F4 + i);
        cp_commit();
    }
    cp_wait<1>();
    __syncthreads();   // chunk1 ready
    gemm_chunk(wbuf + KCH * H3, h1s, KCH, eb, lane, acc);
    __syncthreads();
    {   // stage chunk3 into buf1
        float4* d = (float4*)(wbuf + KCH * H3);
        for (int i = tid; i < F4; i += 256) cp_async16(d + i, wsrc + 3 * F4 + i);
        cp_commit();
    }
    cp_wait<1>();
    __syncthreads();   // chunk2 ready
    gemm_chunk(wbuf, h1s, 2 * KCH, eb, lane, acc);
    cp_wait<0>();
    __syncthreads();   // chunk3 ready
    gemm_chunk(wbuf + KCH * H3, h1s, 3 * KCH, eb, lane, acc);

    // Phase C: epilogue — bias + cutoff, gather, scatter
    const float4* xv  = (const float4*)g_x;  // 96 float4 per node row
    const float4* muv = (const float4*)mu;   // 32 float4 per (node,dim) row
    float* outq  = out;
    float* outmu = out + N_NODES * HID;
    const int c4 = lane * 4;

    #pragma unroll
    for (int e8 = 0; e8 < 8; e8++) {
        const int e = eb + e8;
        const float cscale = cuts[e];
        const int src = srcs[e], tgt = tgts[e];

        float fq[4], fr[4], fm[4];
        unpack2(acc[e8][0], fq[0], fq[1]); unpack2(acc[e8][1], fq[2], fq[3]);
        unpack2(acc[e8][2], fr[0], fr[1]); unpack2(acc[e8][3], fr[2], fr[3]);
        unpack2(acc[e8][4], fm[0], fm[1]); unpack2(acc[e8][5], fm[2], fm[3]);
        #pragma unroll
        for (int i = 0; i < 4; i++) {
            fq[i] = (fq[i] + bf2s[c4 + i]) * cscale;
            fr[i] = (fr[i] + bf2s[HID + c4 + i]) * cscale;
            fm[i] = (fm[i] + bf2s[2 * HID + c4 + i]) * cscale;
        }

        // scalar message
        float4 xq = __ldg(xv + src * 96 + lane);
        red_add_v4(outq + tgt * HID + c4,
                   make_float4(xq.x * fq[0], xq.y * fq[1], xq.z * fq[2], xq.w * fq[3]));

        // vector message
        float4 xr = __ldg(xv + src * 96 + 32 + lane);
        float4 xm = __ldg(xv + src * 96 + 64 + lane);
        float xr0 = xr.x * fr[0], xr1 = xr.y * fr[1], xr2 = xr.z * fr[2], xr3 = xr.w * fr[3];
        float xm0 = xm.x * fm[0], xm1 = xm.y * fm[1], xm2 = xm.z * fm[2], xm3 = xm.w * fm[3];
        #pragma unroll
        for (int d = 0; d < 3; d++) {
            float u = uvs[e * 3 + d];
            float4 m4 = __ldg(muv + (src * 3 + d) * 32 + lane);
            red_add_v4(outmu + (tgt * 3 + d) * HID + c4,
                       make_float4(u * xr0 + m4.x * xm0,
                                   u * xr1 + m4.y * xm1,
                                   u * xr2 + m4.z * xm2,
                                   u * xr3 + m4.w * xm3));
        }
    }
}

extern "C" void kernel_launch(void* const* d_in, const int* in_sizes, int n_in,
                              void* d_out, int out_size) {
    const float* q   = (const float*)d_in[0];
    const float* mu  = (const float*)d_in[1];
    const void*  ei  = d_in[2];
    const float* rbf = (const float*)d_in[3];
    const float* uvp = (const float*)d_in[4];
    const float* cut = (const float*)d_in[5];
    const float* W1  = (const float*)d_in[6];
    const float* b1  = (const float*)d_in[7];
    const float* W2  = (const float*)d_in[8];
    const float* b2  = (const float*)d_in[9];
    const float* Wf1 = (const float*)d_in[10];
    const float* bf1 = (const float*)d_in[11];
    const float* Wf2 = (const float*)d_in[12];
    const float* bf2 = (const float*)d_in[13];
    float* out = (float*)d_out;

    cudaFuncSetAttribute(edge_kernel,
                         cudaFuncAttributeMaxDynamicSharedMemorySize, SMEM_EDGE);

    const int total4 = N_NODES * (HID + H3) / 4;
    init_out<<<(total4 + 255) / 256, 256>>>(q, mu, out, (const int*)ei);
    node_mlp<<<N_NODES / 16, 384>>>(q, W1, b1, W2, b2);
    edge_kernel<<<N_EDGES / EPB, 256, SMEM_EDGE>>>(
        (const int*)ei, (const long long*)ei,
        rbf, uvp, cut, Wf1, bf1, Wf2, bf2, mu, out);
}

// round 4
// speedup vs baseline: 1.2175x; 1.2175x over previous
#include <cuda_runtime.h>

#define N_NODES 10000
#define N_EDGES 320000
#define HID 128
#define H3 384
#define NRBF 20
#define EPB 32      // edges per block (edge kernel)
#define KCH 16      // Wf2 k-rows per staged chunk
#define NCHUNK (HID / KCH)   // 8

typedef unsigned long long ull;

// scratch: node MLP output x = silu(q@W1+b1)@W2+b2, [N, 384]
__device__ float g_x[N_NODES * H3];
__device__ int g_idx64;

__device__ __forceinline__ float silu_f(float v) {
    return v / (1.0f + __expf(-v));
}
__device__ __forceinline__ ull pack2(float lo, float hi) {
    ull r;
    asm("mov.b64 %0,{%1,%2};" : "=l"(r) : "f"(lo), "f"(hi));
    return r;
}
__device__ __forceinline__ void unpack2(ull v, float& lo, float& hi) {
    asm("mov.b64 {%0,%1},%2;" : "=f"(lo), "=f"(hi) : "l"(v));
}
// packed f32x2 FMA — ptxas never emits this from C++; 2x fma-pipe throughput
__device__ __forceinline__ ull fma2(ull a, ull b, ull c) {
    ull d;
    asm("fma.rn.f32x2 %0,%1,%2,%3;" : "=l"(d) : "l"(a), "l"(b), "l"(c));
    return d;
}
// vector atomic: 1 red op covers 4 floats
__device__ __forceinline__ void red_add_v4(float* p, float4 v) {
    asm volatile("red.global.add.v4.f32 [%0],{%1,%2,%3,%4};"
                 :: "l"(p), "f"(v.x), "f"(v.y), "f"(v.z), "f"(v.w) : "memory");
}
__device__ __forceinline__ void cp_async16(void* sdst, const void* gsrc) {
    unsigned s = (unsigned)__cvta_generic_to_shared(sdst);
    asm volatile("cp.async.cg.shared.global [%0],[%1],16;" :: "r"(s), "l"(gsrc));
}
__device__ __forceinline__ void cp_commit() {
    asm volatile("cp.async.commit_group;");
}
template <int N>
__device__ __forceinline__ void cp_wait() {
    asm volatile("cp.async.wait_group %0;" :: "n"(N));
}

// ---------------------------------------------------------------------------
// Kernel 1: out = concat(q, mu); detect int32 vs int64 edge_index layout.
// ---------------------------------------------------------------------------
__global__ void init_out(const float* __restrict__ q,
                         const float* __restrict__ mu,
                         float* __restrict__ out,
                         const int* __restrict__ ei32) {
    if (blockIdx.x == 0 && threadIdx.x == 0) {
        int flag = 1;
        #pragma unroll
        for (int i = 0; i < 16; i++)
            if (ei32[2 * i + 1] != 0) flag = 0;
        g_idx64 = flag;
    }
    int i = blockIdx.x * blockDim.x + threadIdx.x;
    const int nq4 = N_NODES * HID / 4;
    const int nm4 = N_NODES * H3 / 4;
    float4* o4 = (float4*)out;
    if (i < nq4)            o4[i] = ((const float4*)q)[i];
    else if (i < nq4 + nm4) o4[i] = ((const float4*)mu)[i - nq4];
}

// ---------------------------------------------------------------------------
// Kernel 2: node MLP with f32x2 packed math. 16 nodes/block (8 packed pairs),
// 384 threads = one output column per thread.
// ---------------------------------------------------------------------------
__global__ __launch_bounds__(384) void node_mlp(const float* __restrict__ q,
                                                const float* __restrict__ W1,
                                                const float* __restrict__ b1,
                                                const float* __restrict__ W2,
                                                const float* __restrict__ b2) {
    __shared__ float qs[16 * HID];  // 8 KB staging
    __shared__ ull qs2[HID * 8];    // 8 KB packed pairs [k][j]
    __shared__ ull t1p[H3 * 8];     // 24 KB packed hidden [k][j]
    const int n0 = blockIdx.x * 16;
    const int tid = threadIdx.x;

    for (int i = tid; i < 16 * HID; i += 384) qs[i] = q[n0 * HID + i];
    __syncthreads();
    for (int i = tid; i < HID * 8; i += 384) {
        int k = i >> 3, j = i & 7;
        qs2[k * 8 + j] = pack2(qs[(2 * j) * HID + k], qs[(2 * j + 1) * HID + k]);
    }
    __syncthreads();

    const int c = tid;  // 0..383
    // layer 1
    {
        ull a[8];
        float bb = __ldg(&b1[c]);
        ull bp = pack2(bb, bb);
        #pragma unroll
        for (int j = 0; j < 8; j++) a[j] = bp;
        #pragma unroll 4
        for (int k = 0; k < HID; k++) {
            float w = __ldg(&W1[k * H3 + c]);
            ull ww = pack2(w, w);
            const ulonglong2* qp = (const ulonglong2*)(qs2 + k * 8);
            ulonglong2 p0 = qp[0], p1 = qp[1], p2 = qp[2], p3 = qp[3];
            a[0] = fma2(p0.x, ww, a[0]); a[1] = fma2(p0.y, ww, a[1]);
            a[2] = fma2(p1.x, ww, a[2]); a[3] = fma2(p1.y, ww, a[3]);
            a[4] = fma2(p2.x, ww, a[4]); a[5] = fma2(p2.y, ww, a[5]);
            a[6] = fma2(p3.x, ww, a[6]); a[7] = fma2(p3.y, ww, a[7]);
        }
        #pragma unroll
        for (int j = 0; j < 8; j++) {
            float lo, hi;
            unpack2(a[j], lo, hi);
            t1p[c * 8 + j] = pack2(silu_f(lo), silu_f(hi));
        }
    }
    __syncthreads();
    // layer 2
    {
        ull a[8];
        float bb = __ldg(&b2[c]);
        ull bp = pack2(bb, bb);
        #pragma unroll
        for (int j = 0; j < 8; j++) a[j] = bp;
        #pragma unroll 4
        for (int k = 0; k < H3; k++) {
            float w = __ldg(&W2[k * H3 + c]);
            ull ww = pack2(w, w);
            const ulonglong2* tp = (const ulonglong2*)(t1p + k * 8);
            ulonglong2 p0 = tp[0], p1 = tp[1], p2 = tp[2], p3 = tp[3];
            a[0] = fma2(p0.x, ww, a[0]); a[1] = fma2(p0.y, ww, a[1]);
            a[2] = fma2(p1.x, ww, a[2]); a[3] = fma2(p1.y, ww, a[3]);
            a[4] = fma2(p2.x, ww, a[4]); a[5] = fma2(p2.y, ww, a[5]);
            a[6] = fma2(p3.x, ww, a[6]); a[7] = fma2(p3.y, ww, a[7]);
        }
        #pragma unroll
        for (int j = 0; j < 8; j++) {
            float lo, hi;
            unpack2(a[j], lo, hi);
            g_x[(n0 + 2 * j) * H3 + c] = lo;
            g_x[(n0 + 2 * j + 1) * H3 + c] = hi;
        }
    }
}

// ---------------------------------------------------------------------------
// Kernel 3: fused edge kernel. 32 edges/block, 8 warps, 4 edges/warp.
// Wf2 staged in smem in 8 chunks of 16 rows, cp.async double-buffered.
// 81 KB smem, <=128 regs -> 2 CTAs/SM so GEMM of one CTA hides the other's
// barriers, staging and epilogue memory phases.
// ---------------------------------------------------------------------------
// dynamic smem layout (floats unless noted):
//   h1s   [EPB][HID]            @ 0      (16384 B)
//   wbuf  [2][KCH][H3]          @ 16384  (49152 B)
//   Wf1s  [NRBF*HID]            @ 65536  (10240 B)
//   rbfs  [EPB*NRBF]            @ 75776  (2560 B)
//   bf1s  [HID]                 @ 78336  (512 B)
//   bf2s  [H3]                  @ 78848  (1536 B)
//   cuts  [EPB]                 @ 80384  (128 B)
//   uvs   [EPB*3]               @ 80512  (384 B)
//   srcs  [EPB] int             @ 80896  (128 B)
//   tgts  [EPB] int             @ 81024  (128 B)
#define SMEM_EDGE 81152

__global__ __launch_bounds__(256, 2) void edge_kernel(
        const int* __restrict__ ei32, const long long* __restrict__ ei64,
        const float* __restrict__ rbf, const float* __restrict__ uv,
        const float* __restrict__ cut,
        const float* __restrict__ Wf1, const float* __restrict__ bf1,
        const float* __restrict__ Wf2, const float* __restrict__ bf2,
        const float* __restrict__ mu, float* __restrict__ out) {
    extern __shared__ char smem[];
    float* h1s  = (float*)smem;
    float* wbuf = (float*)(smem + 16384);
    float* Wf1s = (float*)(smem + 65536);
    float* rbfs = (float*)(smem + 75776);
    float* bf1s = (float*)(smem + 78336);
    float* bf2s = (float*)(smem + 78848);
    float* cuts = (float*)(smem + 80384);
    float* uvs  = (float*)(smem + 80512);
    int*   srcs = (int*)(smem + 80896);
    int*   tgts = (int*)(smem + 81024);

    const int tid = threadIdx.x;
    const int e0 = blockIdx.x * EPB;
    const int F4 = KCH * H3 / 4;  // float4 per chunk = 1536

    // stage Wf2 chunks 0,1 (overlaps with misc loads + phase A)
    const float4* wsrc = (const float4*)Wf2;
    {
        float4* d0 = (float4*)wbuf;
        for (int i = tid; i < F4; i += 256) cp_async16(d0 + i, wsrc + i);
        cp_commit();
        float4* d1 = (float4*)(wbuf + KCH * H3);
        for (int i = tid; i < F4; i += 256) cp_async16(d1 + i, wsrc + F4 + i);
        cp_commit();
    }

    for (int i = tid; i < NRBF * HID; i += 256) Wf1s[i] = Wf1[i];
    for (int i = tid; i < EPB * NRBF; i += 256) rbfs[i] = rbf[e0 * NRBF + i];
    for (int i = tid; i < H3; i += 256)         bf2s[i] = bf2[i];
    if (tid < HID) bf1s[tid] = bf1[tid];
    if (tid < EPB) {
        int e = e0 + tid;
        cuts[tid] = cut[e];
        if (g_idx64) { tgts[tid] = (int)ei64[e]; srcs[tid] = (int)ei64[N_EDGES + e]; }
        else         { tgts[tid] = ei32[e];      srcs[tid] = ei32[N_EDGES + e]; }
    }
    for (int i = tid; i < EPB * 3; i += 256) uvs[i] = uv[e0 * 3 + i];
    __syncthreads();

    // Phase A: h1 = silu(rbf@Wf1+bf1)
    for (int i = tid; i < EPB * HID; i += 256) {
        int e = i >> 7, j = i & 127;
        float a = bf1s[j];
        #pragma unroll
        for (int k = 0; k < NRBF; k++) a += rbfs[e * NRBF + k] * Wf1s[k * HID + j];
        h1s[i] = silu_f(a);
    }

    // Phase B: filter GEMM, 8 double-buffered chunks of 16 k-rows.
    const int warp = tid >> 5, lane = tid & 31;
    const int eb = warp * 4;
    ull acc[4][6];
    #pragma unroll
    for (int a = 0; a < 4; a++)
        #pragma unroll
        for (int b = 0; b < 6; b++) acc[a][b] = 0ull;

    #pragma unroll
    for (int c = 0; c < NCHUNK; c++) {
        if (c == NCHUNK - 1) cp_wait<0>(); else cp_wait<1>();
        __syncthreads();   // chunk c ready (and, for c==0, h1 ready)
        const float* wch = wbuf + (c & 1) * KCH * H3;
        const int kbase = c * KCH;
        #pragma unroll 4
        for (int kk = 0; kk < KCH; kk++) {
            const ulonglong2* row = (const ulonglong2*)(wch + kk * H3);
            ulonglong2 wq = row[lane];
            ulonglong2 wr = row[32 + lane];
            ulonglong2 wm = row[64 + lane];
            const float* hp = h1s + eb * HID + kbase + kk;
            #pragma unroll
            for (int e = 0; e < 4; e++) {
                float h = hp[e * HID];      // warp-uniform broadcast LDS
                ull h2 = pack2(h, h);
                acc[e][0] = fma2(h2, wq.x, acc[e][0]);
                acc[e][1] = fma2(h2, wq.y, acc[e][1]);
                acc[e][2] = fma2(h2, wr.x, acc[e][2]);
                acc[e][3] = fma2(h2, wr.y, acc[e][3]);
                acc[e][4] = fma2(h2, wm.x, acc[e][4]);
                acc[e][5] = fma2(h2, wm.y, acc[e][5]);
            }
        }
        __syncthreads();   // all warps done reading buffer (c&1)
        if (c + 2 < NCHUNK) {
            float4* d = (float4*)(wbuf + (c & 1) * KCH * H3);
            const float4* s = wsrc + (c + 2) * F4;
            for (int i = tid; i < F4; i += 256) cp_async16(d + i, s + i);
            cp_commit();
        }
    }

    // Phase C: epilogue — bias + cutoff, gather, scatter
    const float4* xv  = (const float4*)g_x;  // 96 float4 per node row
    const float4* muv = (const float4*)mu;   // 32 float4 per (node,dim) row
    float* outq  = out;
    float* outmu = out + N_NODES * HID;
    const int c4 = lane * 4;

    #pragma unroll
    for (int e4 = 0; e4 < 4; e4++) {
        const int e = eb + e4;
        const float cscale = cuts[e];
        const int src = srcs[e], tgt = tgts[e];

        float fq[4], fr[4], fm[4];
        unpack2(acc[e4][0], fq[0], fq[1]); unpack2(acc[e4][1], fq[2], fq[3]);
        unpack2(acc[e4][2], fr[0], fr[1]); unpack2(acc[e4][3], fr[2], fr[3]);
        unpack2(acc[e4][4], fm[0], fm[1]); unpack2(acc[e4][5], fm[2], fm[3]);
        #pragma unroll
        for (int i = 0; i < 4; i++) {
            fq[i] = (fq[i] + bf2s[c4 + i]) * cscale;
            fr[i] = (fr[i] + bf2s[HID + c4 + i]) * cscale;
            fm[i] = (fm[i] + bf2s[2 * HID + c4 + i]) * cscale;
        }

        // scalar message
        float4 xq = __ldg(xv + src * 96 + lane);
        red_add_v4(outq + tgt * HID + c4,
                   make_float4(xq.x * fq[0], xq.y * fq[1], xq.z * fq[2], xq.w * fq[3]));

        // vector message
        float4 xr = __ldg(xv + src * 96 + 32 + lane);
        float4 xm = __ldg(xv + src * 96 + 64 + lane);
        float xr0 = xr.x * fr[0], xr1 = xr.y * fr[1], xr2 = xr.z * fr[2], xr3 = xr.w * fr[3];
        float xm0 = xm.x * fm[0], xm1 = xm.y * fm[1], xm2 = xm.z * fm[2], xm3 = xm.w * fm[3];
        #pragma unroll
        for (int d = 0; d < 3; d++) {
            float u = uvs[e * 3 + d];
            float4 m4 = __ldg(muv + (src * 3 + d) * 32 + lane);
            red_add_v4(outmu + (tgt * 3 + d) * HID + c4,
                       make_float4(u * xr0 + m4.x * xm0,
                                   u * xr1 + m4.y * xm1,
                                   u * xr2 + m4.z * xm2,
                                   u * xr3 + m4.w * xm3));
        }
    }
}

extern "C" void kernel_launch(void* const* d_in, const int* in_sizes, int n_in,
                              void* d_out, int out_size) {
    const float* q   = (const float*)d_in[0];
    const float* mu  = (const float*)d_in[1];
    const void*  ei  = d_in[2];
    const float* rbf = (const float*)d_in[3];
    const float* uvp = (const float*)d_in[4];
    const float* cut = (const float*)d_in[5];
    const float* W1  = (const float*)d_in[6];
    const float* b1  = (const float*)d_in[7];
    const float* W2  = (const float*)d_in[8];
    const float* b2  = (const float*)d_in[9];
    const float* Wf1 = (const float*)d_in[10];
    const float* bf1 = (const float*)d_in[11];
    const float* Wf2 = (const float*)d_in[12];
    const float* bf2 = (const float*)d_in[13];
    float* out = (float*)d_out;

    cudaFuncSetAttribute(edge_kernel,
                         cudaFuncAttributeMaxDynamicSharedMemorySize, SMEM_EDGE);

    const int total4 = N_NODES * (HID + H3) / 4;
    init_out<<<(total4 + 255) / 256, 256>>>(q, mu, out, (const int*)ei);
    node_mlp<<<N_NODES / 16, 384>>>(q, W1, b1, W2, b2);
    edge_kernel<<<N_EDGES / EPB, 256, SMEM_EDGE>>>(
        (const int*)ei, (const long long*)ei,
        rbf, uvp, cut, Wf1, bf1, Wf2, bf2, mu, out);
}

// round 5
// speedup vs baseline: 1.2180x; 1.0004x over previous
#include <cuda_runtime.h>

#define N_NODES 10000
#define N_EDGES 320000
#define HID 128
#define H3 384
#define NRBF 20
#define EPB 32      // edges per block (edge kernel)
#define KCH 16      // Wf2 k-rows per staged chunk
#define NCHUNK (HID / KCH)   // 8

typedef unsigned long long ull;

// scratch: node MLP output x = silu(q@W1+b1)@W2+b2, [N, 384]
__device__ float g_x[N_NODES * H3];
__device__ int g_idx64;

__device__ __forceinline__ float silu_f(float v) {
    return v / (1.0f + __expf(-v));
}
__device__ __forceinline__ ull pack2(float lo, float hi) {
    ull r;
    asm("mov.b64 %0,{%1,%2};" : "=l"(r) : "f"(lo), "f"(hi));
    return r;
}
__device__ __forceinline__ void unpack2(ull v, float& lo, float& hi) {
    asm("mov.b64 {%0,%1},%2;" : "=f"(lo), "=f"(hi) : "l"(v));
}
// packed f32x2 FMA — ptxas never emits this from C++; 2x fma-pipe throughput
__device__ __forceinline__ ull fma2(ull a, ull b, ull c) {
    ull d;
    asm("fma.rn.f32x2 %0,%1,%2,%3;" : "=l"(d) : "l"(a), "l"(b), "l"(c));
    return d;
}
// vector atomic: 1 red op covers 4 floats
__device__ __forceinline__ void red_add_v4(float* p, float4 v) {
    asm volatile("red.global.add.v4.f32 [%0],{%1,%2,%3,%4};"
                 :: "l"(p), "f"(v.x), "f"(v.y), "f"(v.z), "f"(v.w) : "memory");
}
__device__ __forceinline__ void cp_async16(void* sdst, const void* gsrc) {
    unsigned s = (unsigned)__cvta_generic_to_shared(sdst);
    asm volatile("cp.async.cg.shared.global [%0],[%1],16;" :: "r"(s), "l"(gsrc));
}
__device__ __forceinline__ void cp_commit() {
    asm volatile("cp.async.commit_group;");
}
template <int N>
__device__ __forceinline__ void cp_wait() {
    asm volatile("cp.async.wait_group %0;" :: "n"(N));
}

// ---------------------------------------------------------------------------
// Kernel 1: out = concat(q, mu); detect int32 vs int64 edge_index layout.
// ---------------------------------------------------------------------------
__global__ void init_out(const float* __restrict__ q,
                         const float* __restrict__ mu,
                         float* __restrict__ out,
                         const int* __restrict__ ei32) {
    if (blockIdx.x == 0 && threadIdx.x == 0) {
        int flag = 1;
        #pragma unroll
        for (int i = 0; i < 16; i++)
            if (ei32[2 * i + 1] != 0) flag = 0;
        g_idx64 = flag;
    }
    int i = blockIdx.x * blockDim.x + threadIdx.x;
    const int nq4 = N_NODES * HID / 4;
    const int nm4 = N_NODES * H3 / 4;
    float4* o4 = (float4*)out;
    if (i < nq4)            o4[i] = ((const float4*)q)[i];
    else if (i < nq4 + nm4) o4[i] = ((const float4*)mu)[i - nq4];
}

// ---------------------------------------------------------------------------
// Kernel 2: node MLP with f32x2 packed math. 16 nodes/block (8 packed pairs),
// 384 threads = one output column per thread.
// ---------------------------------------------------------------------------
__global__ __launch_bounds__(384) void node_mlp(const float* __restrict__ q,
                                                const float* __restrict__ W1,
                                                const float* __restrict__ b1,
                                                const float* __restrict__ W2,
                                                const float* __restrict__ b2) {
    __shared__ float qs[16 * HID];  // 8 KB staging
    __shared__ ull qs2[HID * 8];    // 8 KB packed pairs [k][j]
    __shared__ ull t1p[H3 * 8];     // 24 KB packed hidden [k][j]
    const int n0 = blockIdx.x * 16;
    const int tid = threadIdx.x;

    for (int i = tid; i < 16 * HID; i += 384) qs[i] = q[n0 * HID + i];
    __syncthreads();
    for (int i = tid; i < HID * 8; i += 384) {
        int k = i >> 3, j = i & 7;
        qs2[k * 8 + j] = pack2(qs[(2 * j) * HID + k], qs[(2 * j + 1) * HID + k]);
    }
    __syncthreads();

    const int c = tid;  // 0..383
    // layer 1
    {
        ull a[8];
        float bb = __ldg(&b1[c]);
        ull bp = pack2(bb, bb);
        #pragma unroll
        for (int j = 0; j < 8; j++) a[j] = bp;
        #pragma unroll 4
        for (int k = 0; k < HID; k++) {
            float w = __ldg(&W1[k * H3 + c]);
            ull ww = pack2(w, w);
            const ulonglong2* qp = (const ulonglong2*)(qs2 + k * 8);
            ulonglong2 p0 = qp[0], p1 = qp[1], p2 = qp[2], p3 = qp[3];
            a[0] = fma2(p0.x, ww, a[0]); a[1] = fma2(p0.y, ww, a[1]);
            a[2] = fma2(p1.x, ww, a[2]); a[3] = fma2(p1.y, ww, a[3]);
            a[4] = fma2(p2.x, ww, a[4]); a[5] = fma2(p2.y, ww, a[5]);
            a[6] = fma2(p3.x, ww, a[6]); a[7] = fma2(p3.y, ww, a[7]);
        }
        #pragma unroll
        for (int j = 0; j < 8; j++) {
            float lo, hi;
            unpack2(a[j], lo, hi);
            t1p[c * 8 + j] = pack2(silu_f(lo), silu_f(hi));
        }
    }
    __syncthreads();
    // layer 2
    {
        ull a[8];
        float bb = __ldg(&b2[c]);
        ull bp = pack2(bb, bb);
        #pragma unroll
        for (int j = 0; j < 8; j++) a[j] = bp;
        #pragma unroll 4
        for (int k = 0; k < H3; k++) {
            float w = __ldg(&W2[k * H3 + c]);
            ull ww = pack2(w, w);
            const ulonglong2* tp = (const ulonglong2*)(t1p + k * 8);
            ulonglong2 p0 = tp[0], p1 = tp[1], p2 = tp[2], p3 = tp[3];
            a[0] = fma2(p0.x, ww, a[0]); a[1] = fma2(p0.y, ww, a[1]);
            a[2] = fma2(p1.x, ww, a[2]); a[3] = fma2(p1.y, ww, a[3]);
            a[4] = fma2(p2.x, ww, a[4]); a[5] = fma2(p2.y, ww, a[5]);
            a[6] = fma2(p3.x, ww, a[6]); a[7] = fma2(p3.y, ww, a[7]);
        }
        #pragma unroll
        for (int j = 0; j < 8; j++) {
            float lo, hi;
            unpack2(a[j], lo, hi);
            g_x[(n0 + 2 * j) * H3 + c] = lo;
            g_x[(n0 + 2 * j + 1) * H3 + c] = hi;
        }
    }
}

// ---------------------------------------------------------------------------
// Kernel 3: fused edge kernel. 32 edges/block, 8 warps, 4 edges/warp.
// Wf2 staged in smem in 8 chunks of 16 rows, cp.async double-buffered.
// 81 KB smem, <=128 regs -> 2 CTAs/SM so GEMM of one CTA hides the other's
// barriers, staging and epilogue memory phases.
// ---------------------------------------------------------------------------
// dynamic smem layout (floats unless noted):
//   h1s   [EPB][HID]            @ 0      (16384 B)
//   wbuf  [2][KCH][H3]          @ 16384  (49152 B)
//   Wf1s  [NRBF*HID]            @ 65536  (10240 B)
//   rbfs  [EPB*NRBF]            @ 75776  (2560 B)
//   bf1s  [HID]                 @ 78336  (512 B)
//   bf2s  [H3]                  @ 78848  (1536 B)
//   cuts  [EPB]                 @ 80384  (128 B)
//   uvs   [EPB*3]               @ 80512  (384 B)
//   srcs  [EPB] int             @ 80896  (128 B)
//   tgts  [EPB] int             @ 81024  (128 B)
#define SMEM_EDGE 81152

__global__ __launch_bounds__(256, 2) void edge_kernel(
        const int* __restrict__ ei32, const long long* __restrict__ ei64,
        const float* __restrict__ rbf, const float* __restrict__ uv,
        const float* __restrict__ cut,
        const float* __restrict__ Wf1, const float* __restrict__ bf1,
        const float* __restrict__ Wf2, const float* __restrict__ bf2,
        const float* __restrict__ mu, float* __restrict__ out) {
    extern __shared__ char smem[];
    float* h1s  = (float*)smem;
    float* wbuf = (float*)(smem + 16384);
    float* Wf1s = (float*)(smem + 65536);
    float* rbfs = (float*)(smem + 75776);
    float* bf1s = (float*)(smem + 78336);
    float* bf2s = (float*)(smem + 78848);
    float* cuts = (float*)(smem + 80384);
    float* uvs  = (float*)(smem + 80512);
    int*   srcs = (int*)(smem + 80896);
    int*   tgts = (int*)(smem + 81024);

    const int tid = threadIdx.x;
    const int e0 = blockIdx.x * EPB;
    const int F4 = KCH * H3 / 4;  // float4 per chunk = 1536

    // stage Wf2 chunks 0,1 (overlaps with misc loads + phase A)
    const float4* wsrc = (const float4*)Wf2;
    {
        float4* d0 = (float4*)wbuf;
        for (int i = tid; i < F4; i += 256) cp_async16(d0 + i, wsrc + i);
        cp_commit();
        float4* d1 = (float4*)(wbuf + KCH * H3);
        for (int i = tid; i < F4; i += 256) cp_async16(d1 + i, wsrc + F4 + i);
        cp_commit();
    }

    for (int i = tid; i < NRBF * HID; i += 256) Wf1s[i] = Wf1[i];
    for (int i = tid; i < EPB * NRBF; i += 256) rbfs[i] = rbf[e0 * NRBF + i];
    for (int i = tid; i < H3; i += 256)         bf2s[i] = bf2[i];
    if (tid < HID) bf1s[tid] = bf1[tid];
    if (tid < EPB) {
        int e = e0 + tid;
        cuts[tid] = cut[e];
        if (g_idx64) { tgts[tid] = (int)ei64[e]; srcs[tid] = (int)ei64[N_EDGES + e]; }
        else         { tgts[tid] = ei32[e];      srcs[tid] = ei32[N_EDGES + e]; }
    }
    for (int i = tid; i < EPB * 3; i += 256) uvs[i] = uv[e0 * 3 + i];
    __syncthreads();

    // Phase A: h1 = silu(rbf@Wf1+bf1)
    for (int i = tid; i < EPB * HID; i += 256) {
        int e = i >> 7, j = i & 127;
        float a = bf1s[j];
        #pragma unroll
        for (int k = 0; k < NRBF; k++) a += rbfs[e * NRBF + k] * Wf1s[k * HID + j];
        h1s[i] = silu_f(a);
    }

    // Phase B: filter GEMM, 8 double-buffered chunks of 16 k-rows.
    const int warp = tid >> 5, lane = tid & 31;
    const int eb = warp * 4;
    ull acc[4][6];
    #pragma unroll
    for (int a = 0; a < 4; a++)
        #pragma unroll
        for (int b = 0; b < 6; b++) acc[a][b] = 0ull;

    #pragma unroll
    for (int c = 0; c < NCHUNK; c++) {
        if (c == NCHUNK - 1) cp_wait<0>(); else cp_wait<1>();
        __syncthreads();   // chunk c ready (and, for c==0, h1 ready)
        const float* wch = wbuf + (c & 1) * KCH * H3;
        const int kbase = c * KCH;
        #pragma unroll 4
        for (int kk = 0; kk < KCH; kk++) {
            const ulonglong2* row = (const ulonglong2*)(wch + kk * H3);
            ulonglong2 wq = row[lane];
            ulonglong2 wr = row[32 + lane];
            ulonglong2 wm = row[64 + lane];
            const float* hp = h1s + eb * HID + kbase + kk;
            #pragma unroll
            for (int e = 0; e < 4; e++) {
                float h = hp[e * HID];      // warp-uniform broadcast LDS
                ull h2 = pack2(h, h);
                acc[e][0] = fma2(h2, wq.x, acc[e][0]);
                acc[e][1] = fma2(h2, wq.y, acc[e][1]);
                acc[e][2] = fma2(h2, wr.x, acc[e][2]);
                acc[e][3] = fma2(h2, wr.y, acc[e][3]);
                acc[e][4] = fma2(h2, wm.x, acc[e][4]);
                acc[e][5] = fma2(h2, wm.y, acc[e][5]);
            }
        }
        __syncthreads();   // all warps done reading buffer (c&1)
        if (c + 2 < NCHUNK) {
            float4* d = (float4*)(wbuf + (c & 1) * KCH * H3);
            const float4* s = wsrc + (c + 2) * F4;
            for (int i = tid; i < F4; i += 256) cp_async16(d + i, s + i);
            cp_commit();
        }
    }

    // Phase C: epilogue — bias + cutoff, gather, scatter
    const float4* xv  = (const float4*)g_x;  // 96 float4 per node row
    const float4* muv = (const float4*)mu;   // 32 float4 per (node,dim) row
    float* outq  = out;
    float* outmu = out + N_NODES * HID;
    const int c4 = lane * 4;

    #pragma unroll
    for (int e4 = 0; e4 < 4; e4++) {
        const int e = eb + e4;
        const float cscale = cuts[e];
        const int src = srcs[e], tgt = tgts[e];

        float fq[4], fr[4], fm[4];
        unpack2(acc[e4][0], fq[0], fq[1]); unpack2(acc[e4][1], fq[2], fq[3]);
        unpack2(acc[e4][2], fr[0], fr[1]); unpack2(acc[e4][3], fr[2], fr[3]);
        unpack2(acc[e4][4], fm[0], fm[1]); unpack2(acc[e4][5], fm[2], fm[3]);
        #pragma unroll
        for (int i = 0; i < 4; i++) {
            fq[i] = (fq[i] + bf2s[c4 + i]) * cscale;
            fr[i] = (fr[i] + bf2s[HID + c4 + i]) * cscale;
            fm[i] = (fm[i] + bf2s[2 * HID + c4 + i]) * cscale;
        }

        // scalar message
        float4 xq = __ldg(xv + src * 96 + lane);
        red_add_v4(outq + tgt * HID + c4,
                   make_float4(xq.x * fq[0], xq.y * fq[1], xq.z * fq[2], xq.w * fq[3]));

        // vector message
        float4 xr = __ldg(xv + src * 96 + 32 + lane);
        float4 xm = __ldg(xv + src * 96 + 64 + lane);
        float xr0 = xr.x * fr[0], xr1 = xr.y * fr[1], xr2 = xr.z * fr[2], xr3 = xr.w * fr[3];
        float xm0 = xm.x * fm[0], xm1 = xm.y * fm[1], xm2 = xm.z * fm[2], xm3 = xm.w * fm[3];
        #pragma unroll
        for (int d = 0; d < 3; d++) {
            float u = uvs[e * 3 + d];
            float4 m4 = __ldg(muv + (src * 3 + d) * 32 + lane);
            red_add_v4(outmu + (tgt * 3 + d) * HID + c4,
                       make_float4(u * xr0 + m4.x * xm0,
                                   u * xr1 + m4.y * xm1,
                                   u * xr2 + m4.z * xm2,
                                   u * xr3 + m4.w * xm3));
        }
    }
}

extern "C" void kernel_launch(void* const* d_in, const int* in_sizes, int n_in,
                              void* d_out, int out_size) {
    const float* q   = (const float*)d_in[0];
    const float* mu  = (const float*)d_in[1];
    const void*  ei  = d_in[2];
    const float* rbf = (const float*)d_in[3];
    const float* uvp = (const float*)d_in[4];
    const float* cut = (const float*)d_in[5];
    const float* W1  = (const float*)d_in[6];
    const float* b1  = (const float*)d_in[7];
    const float* W2  = (const float*)d_in[8];
    const float* b2  = (const float*)d_in[9];
    const float* Wf1 = (const float*)d_in[10];
    const float* bf1 = (const float*)d_in[11];
    const float* Wf2 = (const float*)d_in[12];
    const float* bf2 = (const float*)d_in[13];
    float* out = (float*)d_out;

    cudaFuncSetAttribute(edge_kernel,
                         cudaFuncAttributeMaxDynamicSharedMemorySize, SMEM_EDGE);

    const int total4 = N_NODES * (HID + H3) / 4;
    init_out<<<(total4 + 255) / 256, 256>>>(q, mu, out, (const int*)ei);
    node_mlp<<<N_NODES / 16, 384>>>(q, W1, b1, W2, b2);
    edge_kernel<<<N_EDGES / EPB, 256, SMEM_EDGE>>>(
        (const int*)ei, (const long long*)ei,
        rbf, uvp, cut, Wf1, bf1, Wf2, bf2, mu, out);
}

// round 6
// speedup vs baseline: 1.2527x; 1.0285x over previous
#include <cuda_runtime.h>

#define N_NODES 10000
#define N_EDGES 320000
#define HID 128
#define H3 384
#define NRBF 20
#define EPB 32      // edges per block (edge kernel)
#define KCH 16      // Wf2 k-rows per staged chunk
#define NCHUNK (HID / KCH)   // 8

typedef unsigned long long ull;

// scratch: node MLP output x = silu(q@W1+b1)@W2+b2, [N, 384]
__device__ float g_x[N_NODES * H3];
__device__ int g_idx64;

__device__ __forceinline__ float silu_f(float v) {
    return v / (1.0f + __expf(-v));
}
__device__ __forceinline__ ull pack2(float lo, float hi) {
    ull r;
    asm("mov.b64 %0,{%1,%2};" : "=l"(r) : "f"(lo), "f"(hi));
    return r;
}
__device__ __forceinline__ void unpack2(ull v, float& lo, float& hi) {
    asm("mov.b64 {%0,%1},%2;" : "=f"(lo), "=f"(hi) : "l"(v));
}
// packed f32x2 FMA — ptxas never emits this from C++; 2x fma-pipe throughput
__device__ __forceinline__ ull fma2(ull a, ull b, ull c) {
    ull d;
    asm("fma.rn.f32x2 %0,%1,%2,%3;" : "=l"(d) : "l"(a), "l"(b), "l"(c));
    return d;
}
// vector atomics
__device__ __forceinline__ void red_add_v2(float* p, float a, float b) {
    asm volatile("red.global.add.v2.f32 [%0],{%1,%2};"
                 :: "l"(p), "f"(a), "f"(b) : "memory");
}
__device__ __forceinline__ void cp_async16(void* sdst, const void* gsrc) {
    unsigned s = (unsigned)__cvta_generic_to_shared(sdst);
    asm volatile("cp.async.cg.shared.global [%0],[%1],16;" :: "r"(s), "l"(gsrc));
}
__device__ __forceinline__ void cp_commit() {
    asm volatile("cp.async.commit_group;");
}
template <int N>
__device__ __forceinline__ void cp_wait() {
    asm volatile("cp.async.wait_group %0;" :: "n"(N));
}

// ---------------------------------------------------------------------------
// Kernel 1: out = concat(q, mu); detect int32 vs int64 edge_index layout.
// ---------------------------------------------------------------------------
__global__ void init_out(const float* __restrict__ q,
                         const float* __restrict__ mu,
                         float* __restrict__ out,
                         const int* __restrict__ ei32) {
    if (blockIdx.x == 0 && threadIdx.x == 0) {
        int flag = 1;
        #pragma unroll
        for (int i = 0; i < 16; i++)
            if (ei32[2 * i + 1] != 0) flag = 0;
        g_idx64 = flag;
    }
    int i = blockIdx.x * blockDim.x + threadIdx.x;
    const int nq4 = N_NODES * HID / 4;
    const int nm4 = N_NODES * H3 / 4;
    float4* o4 = (float4*)out;
    if (i < nq4)            o4[i] = ((const float4*)q)[i];
    else if (i < nq4 + nm4) o4[i] = ((const float4*)mu)[i - nq4];
}

// ---------------------------------------------------------------------------
// Kernel 2: node MLP with f32x2 packed math. 16 nodes/block (8 packed pairs),
// 384 threads = one output column per thread.
// ---------------------------------------------------------------------------
__global__ __launch_bounds__(384) void node_mlp(const float* __restrict__ q,
                                                const float* __restrict__ W1,
                                                const float* __restrict__ b1,
                                                const float* __restrict__ W2,
                                                const float* __restrict__ b2) {
    __shared__ float qs[16 * HID];  // 8 KB staging
    __shared__ ull qs2[HID * 8];    // 8 KB packed pairs [k][j]
    __shared__ ull t1p[H3 * 8];     // 24 KB packed hidden [k][j]
    const int n0 = blockIdx.x * 16;
    const int tid = threadIdx.x;

    for (int i = tid; i < 16 * HID; i += 384) qs[i] = q[n0 * HID + i];
    __syncthreads();
    for (int i = tid; i < HID * 8; i += 384) {
        int k = i >> 3, j = i & 7;
        qs2[k * 8 + j] = pack2(qs[(2 * j) * HID + k], qs[(2 * j + 1) * HID + k]);
    }
    __syncthreads();

    const int c = tid;  // 0..383
    // layer 1
    {
        ull a[8];
        float bb = __ldg(&b1[c]);
        ull bp = pack2(bb, bb);
        #pragma unroll
        for (int j = 0; j < 8; j++) a[j] = bp;
        #pragma unroll 4
        for (int k = 0; k < HID; k++) {
            float w = __ldg(&W1[k * H3 + c]);
            ull ww = pack2(w, w);
            const ulonglong2* qp = (const ulonglong2*)(qs2 + k * 8);
            ulonglong2 p0 = qp[0], p1 = qp[1], p2 = qp[2], p3 = qp[3];
            a[0] = fma2(p0.x, ww, a[0]); a[1] = fma2(p0.y, ww, a[1]);
            a[2] = fma2(p1.x, ww, a[2]); a[3] = fma2(p1.y, ww, a[3]);
            a[4] = fma2(p2.x, ww, a[4]); a[5] = fma2(p2.y, ww, a[5]);
            a[6] = fma2(p3.x, ww, a[6]); a[7] = fma2(p3.y, ww, a[7]);
        }
        #pragma unroll
        for (int j = 0; j < 8; j++) {
            float lo, hi;
            unpack2(a[j], lo, hi);
            t1p[c * 8 + j] = pack2(silu_f(lo), silu_f(hi));
        }
    }
    __syncthreads();
    // layer 2
    {
        ull a[8];
        float bb = __ldg(&b2[c]);
        ull bp = pack2(bb, bb);
        #pragma unroll
        for (int j = 0; j < 8; j++) a[j] = bp;
        #pragma unroll 4
        for (int k = 0; k < H3; k++) {
            float w = __ldg(&W2[k * H3 + c]);
            ull ww = pack2(w, w);
            const ulonglong2* tp = (const ulonglong2*)(t1p + k * 8);
            ulonglong2 p0 = tp[0], p1 = tp[1], p2 = tp[2], p3 = tp[3];
            a[0] = fma2(p0.x, ww, a[0]); a[1] = fma2(p0.y, ww, a[1]);
            a[2] = fma2(p1.x, ww, a[2]); a[3] = fma2(p1.y, ww, a[3]);
            a[4] = fma2(p2.x, ww, a[4]); a[5] = fma2(p2.y, ww, a[5]);
            a[6] = fma2(p3.x, ww, a[6]); a[7] = fma2(p3.y, ww, a[7]);
        }
        #pragma unroll
        for (int j = 0; j < 8; j++) {
            float lo, hi;
            unpack2(a[j], lo, hi);
            g_x[(n0 + 2 * j) * H3 + c] = lo;
            g_x[(n0 + 2 * j + 1) * H3 + c] = hi;
        }
    }
}

// ---------------------------------------------------------------------------
// Kernel 3: fused edge kernel. 32 edges/block, 8 warps.
// Warp layout: colgroup g = warp>>2 (half of each 128-col part),
//              edge group  = warp&3 (8 edges each).
// Lane owns 2 consecutive cols per part (ull weights via LDS.64) -> weight
// LDS traffic per fma2 halved vs 4-edge/LDS.128 scheme; h broadcasts
// vectorized as float4 per 4 k-steps. Crossbar demand ~128 cyc/SM/k vs
// 192 fma cyc/SM/k -> fma-bound.
// ---------------------------------------------------------------------------
// dynamic smem layout (floats unless noted):
//   h1s   [EPB][HID]            @ 0      (16384 B)
//   wbuf  [2][KCH][H3]          @ 16384  (49152 B)
//   Wf1s  [NRBF*HID]            @ 65536  (10240 B)
//   rbfs  [EPB*NRBF]            @ 75776  (2560 B)
//   bf1s  [HID]                 @ 78336  (512 B)
//   bf2s  [H3]                  @ 78848  (1536 B)
//   cuts  [EPB]                 @ 80384  (128 B)
//   uvs   [EPB*3]               @ 80512  (384 B)
//   srcs  [EPB] int             @ 80896  (128 B)
//   tgts  [EPB] int             @ 81024  (128 B)
#define SMEM_EDGE 81152

__global__ __launch_bounds__(256, 2) void edge_kernel(
        const int* __restrict__ ei32, const long long* __restrict__ ei64,
        const float* __restrict__ rbf, const float* __restrict__ uv,
        const float* __restrict__ cut,
        const float* __restrict__ Wf1, const float* __restrict__ bf1,
        const float* __restrict__ Wf2, const float* __restrict__ bf2,
        const float* __restrict__ mu, float* __restrict__ out) {
    extern __shared__ char smem[];
    float* h1s  = (float*)smem;
    float* wbuf = (float*)(smem + 16384);
    float* Wf1s = (float*)(smem + 65536);
    float* rbfs = (float*)(smem + 75776);
    float* bf1s = (float*)(smem + 78336);
    float* bf2s = (float*)(smem + 78848);
    float* cuts = (float*)(smem + 80384);
    float* uvs  = (float*)(smem + 80512);
    int*   srcs = (int*)(smem + 80896);
    int*   tgts = (int*)(smem + 81024);

    const int tid = threadIdx.x;
    const int e0 = blockIdx.x * EPB;
    const int F4 = KCH * H3 / 4;  // float4 per chunk = 1536

    // stage Wf2 chunks 0,1 (overlaps with misc loads + phase A)
    const float4* wsrc = (const float4*)Wf2;
    {
        float4* d0 = (float4*)wbuf;
        for (int i = tid; i < F4; i += 256) cp_async16(d0 + i, wsrc + i);
        cp_commit();
        float4* d1 = (float4*)(wbuf + KCH * H3);
        for (int i = tid; i < F4; i += 256) cp_async16(d1 + i, wsrc + F4 + i);
        cp_commit();
    }

    for (int i = tid; i < NRBF * HID; i += 256) Wf1s[i] = Wf1[i];
    for (int i = tid; i < EPB * NRBF; i += 256) rbfs[i] = rbf[e0 * NRBF + i];
    for (int i = tid; i < H3; i += 256)         bf2s[i] = bf2[i];
    if (tid < HID) bf1s[tid] = bf1[tid];
    if (tid < EPB) {
        int e = e0 + tid;
        cuts[tid] = cut[e];
        if (g_idx64) { tgts[tid] = (int)ei64[e]; srcs[tid] = (int)ei64[N_EDGES + e]; }
        else         { tgts[tid] = ei32[e];      srcs[tid] = ei32[N_EDGES + e]; }
    }
    for (int i = tid; i < EPB * 3; i += 256) uvs[i] = uv[e0 * 3 + i];
    __syncthreads();

    // Phase A: h1 = silu(rbf@Wf1+bf1)
    for (int i = tid; i < EPB * HID; i += 256) {
        int e = i >> 7, j = i & 127;
        float a = bf1s[j];
        #pragma unroll
        for (int k = 0; k < NRBF; k++) a += rbfs[e * NRBF + k] * Wf1s[k * HID + j];
        h1s[i] = silu_f(a);
    }

    // Phase B: filter GEMM, 8 double-buffered chunks of 16 k-rows.
    const int warp = tid >> 5, lane = tid & 31;
    const int g = warp >> 2;        // column half (0/1)
    const int eb = (warp & 3) * 8;  // 8 edges per warp
    ull acc[8][3];
    #pragma unroll
    for (int a = 0; a < 8; a++)
        #pragma unroll
        for (int b = 0; b < 3; b++) acc[a][b] = 0ull;

    const int wcol = g * 32 + lane;  // ull index within 64-ull part row

    #pragma unroll
    for (int c = 0; c < NCHUNK; c++) {
        if (c == NCHUNK - 1) cp_wait<0>(); else cp_wait<1>();
        __syncthreads();   // chunk c ready (and, for c==0, h1 ready)
        const float* wch = wbuf + (c & 1) * KCH * H3;
        const float* hp0 = h1s + eb * HID + c * KCH;
        #pragma unroll
        for (int kk4 = 0; kk4 < KCH; kk4 += 4) {
            // vector broadcast of 4 k-values of h for each of 8 edges
            float hv[8][4];
            #pragma unroll
            for (int e = 0; e < 8; e++) {
                float4 t = *(const float4*)(hp0 + e * HID + kk4);
                hv[e][0] = t.x; hv[e][1] = t.y; hv[e][2] = t.z; hv[e][3] = t.w;
            }
            #pragma unroll
            for (int j = 0; j < 4; j++) {
                const ull* row = (const ull*)(wch + (kk4 + j) * H3);
                ull wq = row[wcol];
                ull wr = row[64 + wcol];
                ull wm = row[128 + wcol];
                #pragma unroll
                for (int e = 0; e < 8; e++) {
                    ull h2 = pack2(hv[e][j], hv[e][j]);
                    acc[e][0] = fma2(h2, wq, acc[e][0]);
                    acc[e][1] = fma2(h2, wr, acc[e][1]);
                    acc[e][2] = fma2(h2, wm, acc[e][2]);
                }
            }
        }
        __syncthreads();   // all warps done reading buffer (c&1)
        if (c + 2 < NCHUNK) {
            float4* d = (float4*)(wbuf + (c & 1) * KCH * H3);
            const float4* s = wsrc + (c + 2) * F4;
            for (int i = tid; i < F4; i += 256) cp_async16(d + i, s + i);
            cp_commit();
        }
    }

    // Phase C: epilogue — bias + cutoff, gather, scatter (2 cols/lane)
    float* outq  = out;
    float* outmu = out + N_NODES * HID;
    const int c0 = g * 64 + lane * 2;   // column within a 128-col part

    const float bq0 = bf2s[c0],           bq1 = bf2s[c0 + 1];
    const float br0 = bf2s[HID + c0],     br1 = bf2s[HID + c0 + 1];
    const float bm0 = bf2s[2 * HID + c0], bm1 = bf2s[2 * HID + c0 + 1];

    #pragma unroll
    for (int e8 = 0; e8 < 8; e8++) {
        const int e = eb + e8;
        const float cscale = cuts[e];
        const int src = srcs[e], tgt = tgts[e];

        float fq0, fq1, fr0, fr1, fm0, fm1;
        unpack2(acc[e8][0], fq0, fq1);
        unpack2(acc[e8][1], fr0, fr1);
        unpack2(acc[e8][2], fm0, fm1);
        fq0 = (fq0 + bq0) * cscale; fq1 = (fq1 + bq1) * cscale;
        fr0 = (fr0 + br0) * cscale; fr1 = (fr1 + br1) * cscale;
        fm0 = (fm0 + bm0) * cscale; fm1 = (fm1 + bm1) * cscale;

        const float* xb = g_x + src * H3;
        float2 xq = __ldg((const float2*)(xb + c0));
        red_add_v2(outq + tgt * HID + c0, xq.x * fq0, xq.y * fq1);

        float2 xr = __ldg((const float2*)(xb + HID + c0));
        float2 xm = __ldg((const float2*)(xb + 2 * HID + c0));
        float xr0 = xr.x * fr0, xr1 = xr.y * fr1;
        float xm0 = xm.x * fm0, xm1 = xm.y * fm1;
        #pragma unroll
        for (int d = 0; d < 3; d++) {
            float u = uvs[e * 3 + d];
            float2 m2 = __ldg((const float2*)(mu + (src * 3 + d) * HID + c0));
            red_add_v2(outmu + (tgt * 3 + d) * HID + c0,
                       u * xr0 + m2.x * xm0,
                       u * xr1 + m2.y * xm1);
        }
    }
}

extern "C" void kernel_launch(void* const* d_in, const int* in_sizes, int n_in,
                              void* d_out, int out_size) {
    const float* q   = (const float*)d_in[0];
    const float* mu  = (const float*)d_in[1];
    const void*  ei  = d_in[2];
    const float* rbf = (const float*)d_in[3];
    const float* uvp = (const float*)d_in[4];
    const float* cut = (const float*)d_in[5];
    const float* W1  = (const float*)d_in[6];
    const float* b1  = (const float*)d_in[7];
    const float* W2  = (const float*)d_in[8];
    const float* b2  = (const float*)d_in[9];
    const float* Wf1 = (const float*)d_in[10];
    const float* bf1 = (const float*)d_in[11];
    const float* Wf2 = (const float*)d_in[12];
    const float* bf2 = (const float*)d_in[13];
    float* out = (float*)d_out;

    cudaFuncSetAttribute(edge_kernel,
                         cudaFuncAttributeMaxDynamicSharedMemorySize, SMEM_EDGE);

    const int total4 = N_NODES * (HID + H3) / 4;
    init_out<<<(total4 + 255) / 256, 256>>>(q, mu, out, (const int*)ei);
    node_mlp<<<N_NODES / 16, 384>>>(q, W1, b1, W2, b2);
    edge_kernel<<<N_EDGES / EPB, 256, SMEM_EDGE>>>(
        (const int*)ei, (const long long*)ei,
        rbf, uvp, cut, Wf1, bf1, Wf2, bf2, mu, out);
}

// round 7
// speedup vs baseline: 1.2636x; 1.0087x over previous
#include <cuda_runtime.h>

#define N_NODES 10000
#define N_EDGES 320000
#define HID 128
#define H3 384
#define NRBF 20
#define EPB 32      // edges per block (edge kernel)
#define KCH 16      // Wf2 k-rows per staged chunk
#define NCHUNK (HID / KCH)   // 8

typedef unsigned long long ull;

// scratch
__device__ float g_x[N_NODES * H3];   // node MLP output [N, 384]
__device__ int g_idx64;
__device__ int g_hist[N_NODES];
__device__ int g_cursor[N_NODES];
__device__ int g_perm[N_EDGES];       // edge ids sorted by target

__device__ __forceinline__ float silu_f(float v) {
    return v / (1.0f + __expf(-v));
}
__device__ __forceinline__ ull pack2(float lo, float hi) {
    ull r;
    asm("mov.b64 %0,{%1,%2};" : "=l"(r) : "f"(lo), "f"(hi));
    return r;
}
__device__ __forceinline__ void unpack2(ull v, float& lo, float& hi) {
    asm("mov.b64 {%0,%1},%2;" : "=f"(lo), "=f"(hi) : "l"(v));
}
// packed f32x2 FMA — 2x fma-pipe throughput
__device__ __forceinline__ ull fma2(ull a, ull b, ull c) {
    ull d;
    asm("fma.rn.f32x2 %0,%1,%2,%3;" : "=l"(d) : "l"(a), "l"(b), "l"(c));
    return d;
}
__device__ __forceinline__ void red_add_v2(float* p, float a, float b) {
    asm volatile("red.global.add.v2.f32 [%0],{%1,%2};"
                 :: "l"(p), "f"(a), "f"(b) : "memory");
}
__device__ __forceinline__ void cp_async16(void* sdst, const void* gsrc) {
    unsigned s = (unsigned)__cvta_generic_to_shared(sdst);
    asm volatile("cp.async.cg.shared.global [%0],[%1],16;" :: "r"(s), "l"(gsrc));
}
__device__ __forceinline__ void cp_commit() {
    asm volatile("cp.async.commit_group;");
}
template <int N>
__device__ __forceinline__ void cp_wait() {
    asm volatile("cp.async.wait_group %0;" :: "n"(N));
}

// ---------------------------------------------------------------------------
// Kernel 1: out = concat(q, mu); detect idx dtype; zero histogram.
// ---------------------------------------------------------------------------
__global__ void init_out(const float* __restrict__ q,
                         const float* __restrict__ mu,
                         float* __restrict__ out,
                         const int* __restrict__ ei32) {
    if (blockIdx.x == 0 && threadIdx.x == 0) {
        int flag = 1;
        #pragma unroll
        for (int i = 0; i < 16; i++)
            if (ei32[2 * i + 1] != 0) flag = 0;
        g_idx64 = flag;
    }
    int i = blockIdx.x * blockDim.x + threadIdx.x;
    if (i < N_NODES) g_hist[i] = 0;
    const int nq4 = N_NODES * HID / 4;
    const int nm4 = N_NODES * H3 / 4;
    float4* o4 = (float4*)out;
    if (i < nq4)            o4[i] = ((const float4*)q)[i];
    else if (i < nq4 + nm4) o4[i] = ((const float4*)mu)[i - nq4];
}

// --------------------------- counting sort by target -----------------------
__global__ void hist_kernel(const int* __restrict__ ei32,
                            const long long* __restrict__ ei64) {
    int e = blockIdx.x * blockDim.x + threadIdx.x;
    if (e < N_EDGES) {
        int t = g_idx64 ? (int)ei64[e] : ei32[e];
        atomicAdd(&g_hist[t], 1);
    }
}

__global__ __launch_bounds__(1024) void scan_kernel() {
    // exclusive prefix sum over 10000 bins; 1 block, 10 bins/thread
    __shared__ int part[1024];
    const int tid = threadIdx.x;
    const int base = tid * 10;
    int local[10];
    int s = 0;
    #pragma unroll
    for (int j = 0; j < 10; j++) {
        int v = (base + j < N_NODES) ? g_hist[base + j] : 0;
        local[j] = s;
        s += v;
    }
    part[tid] = s;
    __syncthreads();
    const int own = s;
    for (int d = 1; d < 1024; d <<= 1) {
        int v = (tid >= d) ? part[tid - d] : 0;
        __syncthreads();
        part[tid] += v;
        __syncthreads();
    }
    int excl = part[tid] - own;
    #pragma unroll
    for (int j = 0; j < 10; j++)
        if (base + j < N_NODES) g_cursor[base + j] = excl + local[j];
}

__global__ void scatter_kernel(const int* __restrict__ ei32,
                               const long long* __restrict__ ei64) {
    int e = blockIdx.x * blockDim.x + threadIdx.x;
    if (e < N_EDGES) {
        int t = g_idx64 ? (int)ei64[e] : ei32[e];
        int pos = atomicAdd(&g_cursor[t], 1);
        g_perm[pos] = e;
    }
}

// ---------------------------------------------------------------------------
// Kernel 2: node MLP with f32x2 packed math. 16 nodes/block.
// ---------------------------------------------------------------------------
__global__ __launch_bounds__(384) void node_mlp(const float* __restrict__ q,
                                                const float* __restrict__ W1,
                                                const float* __restrict__ b1,
                                                const float* __restrict__ W2,
                                                const float* __restrict__ b2) {
    __shared__ float qs[16 * HID];
    __shared__ ull qs2[HID * 8];
    __shared__ ull t1p[H3 * 8];
    const int n0 = blockIdx.x * 16;
    const int tid = threadIdx.x;

    for (int i = tid; i < 16 * HID; i += 384) qs[i] = q[n0 * HID + i];
    __syncthreads();
    for (int i = tid; i < HID * 8; i += 384) {
        int k = i >> 3, j = i & 7;
        qs2[k * 8 + j] = pack2(qs[(2 * j) * HID + k], qs[(2 * j + 1) * HID + k]);
    }
    __syncthreads();

    const int c = tid;
    {
        ull a[8];
        float bb = __ldg(&b1[c]);
        ull bp = pack2(bb, bb);
        #pragma unroll
        for (int j = 0; j < 8; j++) a[j] = bp;
        #pragma unroll 4
        for (int k = 0; k < HID; k++) {
            float w = __ldg(&W1[k * H3 + c]);
            ull ww = pack2(w, w);
            const ulonglong2* qp = (const ulonglong2*)(qs2 + k * 8);
            ulonglong2 p0 = qp[0], p1 = qp[1], p2 = qp[2], p3 = qp[3];
            a[0] = fma2(p0.x, ww, a[0]); a[1] = fma2(p0.y, ww, a[1]);
            a[2] = fma2(p1.x, ww, a[2]); a[3] = fma2(p1.y, ww, a[3]);
            a[4] = fma2(p2.x, ww, a[4]); a[5] = fma2(p2.y, ww, a[5]);
            a[6] = fma2(p3.x, ww, a[6]); a[7] = fma2(p3.y, ww, a[7]);
        }
        #pragma unroll
        for (int j = 0; j < 8; j++) {
            float lo, hi;
            unpack2(a[j], lo, hi);
            t1p[c * 8 + j] = pack2(silu_f(lo), silu_f(hi));
        }
    }
    __syncthreads();
    {
        ull a[8];
        float bb = __ldg(&b2[c]);
        ull bp = pack2(bb, bb);
        #pragma unroll
        for (int j = 0; j < 8; j++) a[j] = bp;
        #pragma unroll 4
        for (int k = 0; k < H3; k++) {
            float w = __ldg(&W2[k * H3 + c]);
            ull ww = pack2(w, w);
            const ulonglong2* tp = (const ulonglong2*)(t1p + k * 8);
            ulonglong2 p0 = tp[0], p1 = tp[1], p2 = tp[2], p3 = tp[3];
            a[0] = fma2(p0.x, ww, a[0]); a[1] = fma2(p0.y, ww, a[1]);
            a[2] = fma2(p1.x, ww, a[2]); a[3] = fma2(p1.y, ww, a[3]);
            a[4] = fma2(p2.x, ww, a[4]); a[5] = fma2(p2.y, ww, a[5]);
            a[6] = fma2(p3.x, ww, a[6]); a[7] = fma2(p3.y, ww, a[7]);
        }
        #pragma unroll
        for (int j = 0; j < 8; j++) {
            float lo, hi;
            unpack2(a[j], lo, hi);
            g_x[(n0 + 2 * j) * H3 + c] = lo;
            g_x[(n0 + 2 * j + 1) * H3 + c] = hi;
        }
    }
}

// ---------------------------------------------------------------------------
// Kernel 3: fused edge kernel over TARGET-SORTED edges.
// 32 edges/block via g_perm; warps accumulate messages across runs of equal
// target and flush once per run -> ~8x fewer REDG instructions.
// ---------------------------------------------------------------------------
// dynamic smem layout:
//   h1s   [EPB][HID]            @ 0      (16384 B)
//   wbuf  [2][KCH][H3]          @ 16384  (49152 B)
//   Wf1s  [NRBF*HID]            @ 65536  (10240 B)
//   rbfs  [EPB*NRBF]            @ 75776  (2560 B)
//   bf1s  [HID]                 @ 78336  (512 B)
//   bf2s  [H3]                  @ 78848  (1536 B)
//   cuts  [EPB]                 @ 80384  (128 B)
//   uvs   [EPB*3]               @ 80512  (384 B)
//   srcs  [EPB] int             @ 80896  (128 B)
//   tgts  [EPB] int             @ 81024  (128 B)
//   es    [EPB] int             @ 81152  (128 B)
#define SMEM_EDGE 81280

__global__ __launch_bounds__(256, 2) void edge_kernel(
        const int* __restrict__ ei32, const long long* __restrict__ ei64,
        const float* __restrict__ rbf, const float* __restrict__ uv,
        const float* __restrict__ cut,
        const float* __restrict__ Wf1, const float* __restrict__ bf1,
        const float* __restrict__ Wf2, const float* __restrict__ bf2,
        const float* __restrict__ mu, float* __restrict__ out) {
    extern __shared__ char smem[];
    float* h1s  = (float*)smem;
    float* wbuf = (float*)(smem + 16384);
    float* Wf1s = (float*)(smem + 65536);
    float* rbfs = (float*)(smem + 75776);
    float* bf1s = (float*)(smem + 78336);
    float* bf2s = (float*)(smem + 78848);
    float* cuts = (float*)(smem + 80384);
    float* uvs  = (float*)(smem + 80512);
    int*   srcs = (int*)(smem + 80896);
    int*   tgts = (int*)(smem + 81024);
    int*   es   = (int*)(smem + 81152);

    const int tid = threadIdx.x;
    const int e0 = blockIdx.x * EPB;
    const int F4 = KCH * H3 / 4;  // 1536

    // stage Wf2 chunks 0,1
    const float4* wsrc = (const float4*)Wf2;
    {
        float4* d0 = (float4*)wbuf;
        for (int i = tid; i < F4; i += 256) cp_async16(d0 + i, wsrc + i);
        cp_commit();
        float4* d1 = (float4*)(wbuf + KCH * H3);
        for (int i = tid; i < F4; i += 256) cp_async16(d1 + i, wsrc + F4 + i);
        cp_commit();
    }

    if (tid < EPB) es[tid] = g_perm[e0 + tid];
    for (int i = tid; i < NRBF * HID; i += 256) Wf1s[i] = Wf1[i];
    for (int i = tid; i < H3; i += 256)         bf2s[i] = bf2[i];
    if (tid < HID) bf1s[tid] = bf1[tid];
    __syncthreads();  // es visible

    // per-edge gathers through permutation
    {
        // rbf rows are 80 B = 5 float4 each
        float4* r4 = (float4*)rbfs;
        const float4* rsrc = (const float4*)rbf;
        for (int i = tid; i < EPB * 5; i += 256) {
            int e = es[i / 5];
            r4[i] = __ldg(rsrc + e * 5 + (i % 5));
        }
        for (int i = tid; i < EPB * 3; i += 256) {
            int e = es[i / 3];
            uvs[i] = uv[e * 3 + (i % 3)];
        }
        if (tid < EPB) {
            int e = es[tid];
            cuts[tid] = cut[e];
            if (g_idx64) { tgts[tid] = (int)ei64[e]; srcs[tid] = (int)ei64[N_EDGES + e]; }
            else         { tgts[tid] = ei32[e];      srcs[tid] = ei32[N_EDGES + e]; }
        }
    }
    __syncthreads();

    // Phase A: h1 = silu(rbf@Wf1+bf1)
    for (int i = tid; i < EPB * HID; i += 256) {
        int e = i >> 7, j = i & 127;
        float a = bf1s[j];
        #pragma unroll
        for (int k = 0; k < NRBF; k++) a += rbfs[e * NRBF + k] * Wf1s[k * HID + j];
        h1s[i] = silu_f(a);
    }

    // Phase B: filter GEMM, double-buffered 16-row chunks
    const int warp = tid >> 5, lane = tid & 31;
    const int g = warp >> 2;        // column half (0/1)
    const int eb = (warp & 3) * 8;  // 8 edges per warp
    ull acc[8][3];
    #pragma unroll
    for (int a = 0; a < 8; a++)
        #pragma unroll
        for (int b = 0; b < 3; b++) acc[a][b] = 0ull;

    const int wcol = g * 32 + lane;

    #pragma unroll
    for (int c = 0; c < NCHUNK; c++) {
        if (c == NCHUNK - 1) cp_wait<0>(); else cp_wait<1>();
        __syncthreads();
        const float* wch = wbuf + (c & 1) * KCH * H3;
        const float* hp0 = h1s + eb * HID + c * KCH;
        #pragma unroll
        for (int kk4 = 0; kk4 < KCH; kk4 += 4) {
            float hv[8][4];
            #pragma unroll
            for (int e = 0; e < 8; e++) {
                float4 t = *(const float4*)(hp0 + e * HID + kk4);
                hv[e][0] = t.x; hv[e][1] = t.y; hv[e][2] = t.z; hv[e][3] = t.w;
            }
            #pragma unroll
            for (int j = 0; j < 4; j++) {
                const ull* row = (const ull*)(wch + (kk4 + j) * H3);
                ull wq = row[wcol];
                ull wr = row[64 + wcol];
                ull wm = row[128 + wcol];
                #pragma unroll
                for (int e = 0; e < 8; e++) {
                    ull h2 = pack2(hv[e][j], hv[e][j]);
                    acc[e][0] = fma2(h2, wq, acc[e][0]);
                    acc[e][1] = fma2(h2, wr, acc[e][1]);
                    acc[e][2] = fma2(h2, wm, acc[e][2]);
                }
            }
        }
        __syncthreads();
        if (c + 2 < NCHUNK) {
            float4* d = (float4*)(wbuf + (c & 1) * KCH * H3);
            const float4* s = wsrc + (c + 2) * F4;
            for (int i = tid; i < F4; i += 256) cp_async16(d + i, s + i);
            cp_commit();
        }
    }

    // Phase C: epilogue with run-combined scatter (targets sorted).
    float* outq  = out;
    float* outmu = out + N_NODES * HID;
    const int c0 = g * 64 + lane * 2;

    const float bq0 = bf2s[c0],           bq1 = bf2s[c0 + 1];
    const float br0 = bf2s[HID + c0],     br1 = bf2s[HID + c0 + 1];
    const float bm0 = bf2s[2 * HID + c0], bm1 = bf2s[2 * HID + c0 + 1];

    float sq0 = 0.f, sq1 = 0.f;
    float sv[3][2] = {{0.f,0.f},{0.f,0.f},{0.f,0.f}};

    #pragma unroll
    for (int e8 = 0; e8 < 8; e8++) {
        const int e = eb + e8;
        const float cscale = cuts[e];
        const int src = srcs[e];

        float fq0, fq1, fr0, fr1, fm0, fm1;
        unpack2(acc[e8][0], fq0, fq1);
        unpack2(acc[e8][1], fr0, fr1);
        unpack2(acc[e8][2], fm0, fm1);
        fq0 = (fq0 + bq0) * cscale; fq1 = (fq1 + bq1) * cscale;
        fr0 = (fr0 + br0) * cscale; fr1 = (fr1 + br1) * cscale;
        fm0 = (fm0 + bm0) * cscale; fm1 = (fm1 + bm1) * cscale;

        const float* xb = g_x + src * H3;
        float2 xq = __ldg((const float2*)(xb + c0));
        sq0 += xq.x * fq0; sq1 += xq.y * fq1;

        float2 xr = __ldg((const float2*)(xb + HID + c0));
        float2 xm = __ldg((const float2*)(xb + 2 * HID + c0));
        float xr0 = xr.x * fr0, xr1 = xr.y * fr1;
        float xm0 = xm.x * fm0, xm1 = xm.y * fm1;
        #pragma unroll
        for (int d = 0; d < 3; d++) {
            float u = uvs[e * 3 + d];
            float2 m2 = __ldg((const float2*)(mu + (src * 3 + d) * HID + c0));
            sv[d][0] += u * xr0 + m2.x * xm0;
            sv[d][1] += u * xr1 + m2.y * xm1;
        }

        const int t = tgts[e];
        const bool flush = (e8 == 7) || (tgts[e + 1] != t);  // warp-uniform
        if (flush) {
            red_add_v2(outq + t * HID + c0, sq0, sq1);
            #pragma unroll
            for (int d = 0; d < 3; d++)
                red_add_v2(outmu + (t * 3 + d) * HID + c0, sv[d][0], sv[d][1]);
            sq0 = sq1 = 0.f;
            #pragma unroll
            for (int d = 0; d < 3; d++) { sv[d][0] = 0.f; sv[d][1] = 0.f; }
        }
    }
}

extern "C" void kernel_launch(void* const* d_in, const int* in_sizes, int n_in,
                              void* d_out, int out_size) {
    const float* q   = (const float*)d_in[0];
    const float* mu  = (const float*)d_in[1];
    const void*  ei  = d_in[2];
    const float* rbf = (const float*)d_in[3];
    const float* uvp = (const float*)d_in[4];
    const float* cut = (const float*)d_in[5];
    const float* W1  = (const float*)d_in[6];
    const float* b1  = (const float*)d_in[7];
    const float* W2  = (const float*)d_in[8];
    const float* b2  = (const float*)d_in[9];
    const float* Wf1 = (const float*)d_in[10];
    const float* bf1 = (const float*)d_in[11];
    const float* Wf2 = (const float*)d_in[12];
    const float* bf2 = (const float*)d_in[13];
    float* out = (float*)d_out;

    cudaFuncSetAttribute(edge_kernel,
                         cudaFuncAttributeMaxDynamicSharedMemorySize, SMEM_EDGE);

    const int total4 = N_NODES * (HID + H3) / 4;
    init_out<<<(total4 + 255) / 256, 256>>>(q, mu, out, (const int*)ei);
    hist_kernel<<<(N_EDGES + 255) / 256, 256>>>((const int*)ei, (const long long*)ei);
    scan_kernel<<<1, 1024>>>();
    scatter_kernel<<<(N_EDGES + 255) / 256, 256>>>((const int*)ei, (const long long*)ei);
    node_mlp<<<N_NODES / 16, 384>>>(q, W1, b1, W2, b2);
    edge_kernel<<<N_EDGES / EPB, 256, SMEM_EDGE>>>(
        (const int*)ei, (const long long*)ei,
        rbf, uvp, cut, Wf1, bf1, Wf2, bf2, mu, out);
}